// round 17
// baseline (speedup 1.0000x reference)
#include <cuda_runtime.h>
#include <cuda_fp16.h>
#include <cstdint>
#include <math.h>

// Problem constants
#define Bb 4
#define Ts 2048
#define Cc 1024
#define Hh 16
#define Dd 64
#define Mtot (Bb*Ts)        // 8192
#define Nqkv (3*Cc)         // 3072
#define Kdim Cc             // 1024

// ---------------------------------------------------------------------------
// Scratch (__device__ globals). RULE: referenced ONLY from device code.
// fp16 scheme: A-side operands split hi/lo; B-side operands single fp16.
// ---------------------------------------------------------------------------
__device__ __align__(128) __half g_xhi[Mtot*Kdim];
__device__ __align__(128) __half g_xlo[Mtot*Kdim];
__device__ __align__(128) __half g_wq[Nqkv*Kdim];    // [N][K] single fp16
__device__ __align__(128) __half g_wo[Cc*Kdim];
__device__ __align__(128) __half g_qhi[Bb*Hh*Ts*Dd]; // [b,h,t,d], pre-scaled 1/8
__device__ __align__(128) __half g_qlo[Bb*Hh*Ts*Dd];
__device__ __align__(128) __half g_khi[Bb*Hh*Ts*Dd];
__device__ __align__(128) __half g_klo[Bb*Hh*Ts*Dd];
__device__ __align__(128) __half g_vt[Bb*Hh*Dd*Ts];  // [b,h,d,t] single fp16
__device__ __align__(128) __half g_yhi[Mtot*Kdim];
__device__ __align__(128) __half g_ylo[Mtot*Kdim];

// ---------------------------------------------------------------------------
// Helpers
// ---------------------------------------------------------------------------
#define MMA_F16(c, a, b) asm volatile( \
    "mma.sync.aligned.m16n8k16.row.col.f32.f16.f16.f32 " \
    "{%0,%1,%2,%3}, {%4,%5,%6,%7}, {%8,%9}, {%0,%1,%2,%3};" \
    : "+f"((c)[0]), "+f"((c)[1]), "+f"((c)[2]), "+f"((c)[3]) \
    : "r"((a)[0]), "r"((a)[1]), "r"((a)[2]), "r"((a)[3]), \
      "r"((b)[0]), "r"((b)[1]))

#define CP16(s, g) \
    asm volatile("cp.async.cg.shared.global [%0], [%1], 16;" :: "r"(s), "l"(g))
#define CP_COMMIT() asm volatile("cp.async.commit_group;")
#define CP_WAIT1()  asm volatile("cp.async.wait_group 1;")
#define CP_WAIT0()  asm volatile("cp.async.wait_group 0;")

__device__ __forceinline__ uint32_t smem_to_u32(const void* p) {
    uint32_t a;
    asm("{ .reg .u64 t; cvta.to.shared.u64 t, %1; cvt.u32.u64 %0, t; }"
        : "=r"(a) : "l"(p));
    return a;
}
__device__ __forceinline__ void split2h(float a, __half& h, __half& l) {
    __half hh = __float2half_rn(a);
    l = __float2half_rn(a - __half2float(hh));
    h = hh;
}
__device__ __forceinline__ uint32_t pack2h(__half a, __half b) {
    __half2 p = __halves2half2(a, b);
    return *(uint32_t*)&p;
}

// ---------------------------------------------------------------------------
// x pre-split: fp32 -> g_xhi/g_xlo (fp16)
// ---------------------------------------------------------------------------
__global__ void split_x_kernel(const float* __restrict__ in)
{
    const int i = blockIdx.x * blockDim.x + threadIdx.x;
    float4 v = *(const float4*)&in[(size_t)i * 4];
    __half h0,l0,h1,l1,h2,l2,h3,l3;
    split2h(v.x, h0, l0); split2h(v.y, h1, l1);
    split2h(v.z, h2, l2); split2h(v.w, h3, l3);
    uint2 hh = make_uint2(pack2h(h0, h1), pack2h(h2, h3));
    uint2 ll = make_uint2(pack2h(l0, l1), pack2h(l2, l3));
    *(uint2*)&g_xhi[(size_t)i * 4] = hh;
    *(uint2*)&g_xlo[(size_t)i * 4] = ll;
}

// ---------------------------------------------------------------------------
// Weight transpose to [N][K] single fp16
// ---------------------------------------------------------------------------
template<int MODE, int N>
__global__ void transpose_half_kernel(const float* __restrict__ in)
{
    __half* __restrict__ dst = (MODE == 0) ? g_wq : g_wo;

    __shared__ float t[32][33];
    const int n0 = blockIdx.x * 32, k0 = blockIdx.y * 32;
    #pragma unroll
    for (int i = 0; i < 4; i++) {
        int k = k0 + threadIdx.y + i * 8;
        t[threadIdx.y + i * 8][threadIdx.x] = in[(size_t)k * N + n0 + threadIdx.x];
    }
    __syncthreads();
    #pragma unroll
    for (int i = 0; i < 4; i++) {
        int n = n0 + threadIdx.y + i * 8;
        int k = k0 + threadIdx.x;
        dst[(size_t)n * Kdim + k] = __float2half_rn(t[threadIdx.x][threadIdx.y + i * 8]);
    }
}

#define BM 128
#define BN 128
#define BK 32
#define KPAD 40
#define TILE_E (BM * KPAD)
#define TILE_B (TILE_E * 2)
#define STAGE_B (3 * TILE_B)       // Ahi, Alo, B
#define GEMM_SMEM (2 * STAGE_B)    // 61440 bytes

// ---------------------------------------------------------------------------
// 2-product fp16 warp-MMA GEMM: D = (Ahi+Alo) @ Bfp16, cp.async pipelined.
// MODE 0: A = g_x*, B = g_wq; epilogue splits+scatters q/k (hi/lo) and v^T.
// MODE 1: A = g_y*, B = g_wo; epilogue -> outp fp32.
// ---------------------------------------------------------------------------
template<int MODE, int N>
__global__ __launch_bounds__(256)
void gemm_mma(const float* __restrict__ bias,
              float* __restrict__ outp)
{
    const __half* __restrict__ Ahi = (MODE == 0) ? g_xhi : g_yhi;
    const __half* __restrict__ Alo = (MODE == 0) ? g_xlo : g_ylo;
    const __half* __restrict__ Bp  = (MODE == 0) ? g_wq : g_wo;

    extern __shared__ __align__(16) char smem_raw[];
    __half* smem = (__half*)smem_raw;
    const uint32_t sbase = smem_to_u32(smem_raw);

    const int tid = threadIdx.x;
    const int l = tid & 31;
    const int wid = tid >> 5;
    const int wm = wid & 3;
    const int wn = wid >> 2;
    const int m0 = blockIdx.y * BM;
    const int n0 = blockIdx.x * BN;
    const int qr = l >> 2;
    const int qc = l & 3;

    float acc[2][8][4];
    #pragma unroll
    for (int i = 0; i < 2; i++)
        #pragma unroll
        for (int j = 0; j < 8; j++)
            #pragma unroll
            for (int q = 0; q < 4; q++) acc[i][j][q] = 0.f;

    const int fr = tid >> 2;
    const int fs = (tid & 3) * 8;

    auto issue = [&](int stage, int kc) {
        const int k0 = kc * BK;
        const uint32_t s0 = sbase + (uint32_t)stage * STAGE_B;
        #pragma unroll
        for (int hx = 0; hx < 2; hx++) {
            const int r = fr + hx * 64;
            const uint32_t so = (uint32_t)(r * KPAD + fs) * 2;
            const size_t ga = (size_t)(m0 + r) * Kdim + k0 + fs;
            const size_t gb = (size_t)(n0 + r) * Kdim + k0 + fs;
            CP16(s0 + 0u*TILE_B + so, Ahi + ga);
            CP16(s0 + 1u*TILE_B + so, Alo + ga);
            CP16(s0 + 2u*TILE_B + so, Bp + gb);
        }
        CP_COMMIT();
    };

    const int NC = Kdim / BK;
    issue(0, 0);

    for (int kc = 0; kc < NC; kc++) {
        if (kc + 1 < NC) { issue((kc + 1) & 1, kc + 1); CP_WAIT1(); }
        else             { CP_WAIT0(); }
        __syncthreads();

        const __half* sA0 = smem + (size_t)(kc & 1) * (STAGE_B / 2);
        const __half* sA1 = sA0 + TILE_E;
        const __half* sB  = sA0 + 2 * TILE_E;

        #pragma unroll
        for (int kk = 0; kk < 2; kk++) {
            const int kb = kk * 16 + qc * 2;
            uint32_t bf[8][2];
            #pragma unroll
            for (int nb = 0; nb < 8; nb++) {
                const int nrow = wn * 64 + nb * 8 + qr;
                bf[nb][0] = *(const uint32_t*)&sB[nrow * KPAD + kb];
                bf[nb][1] = *(const uint32_t*)&sB[nrow * KPAD + kb + 8];
            }
            uint32_t ah[2][4], al[2][4];
            #pragma unroll
            for (int mb = 0; mb < 2; mb++) {
                const int arow = wm * 32 + mb * 16 + qr;
                ah[mb][0] = *(const uint32_t*)&sA0[arow * KPAD + kb];
                ah[mb][1] = *(const uint32_t*)&sA0[(arow + 8) * KPAD + kb];
                ah[mb][2] = *(const uint32_t*)&sA0[arow * KPAD + kb + 8];
                ah[mb][3] = *(const uint32_t*)&sA0[(arow + 8) * KPAD + kb + 8];
                al[mb][0] = *(const uint32_t*)&sA1[arow * KPAD + kb];
                al[mb][1] = *(const uint32_t*)&sA1[(arow + 8) * KPAD + kb];
                al[mb][2] = *(const uint32_t*)&sA1[arow * KPAD + kb + 8];
                al[mb][3] = *(const uint32_t*)&sA1[(arow + 8) * KPAD + kb + 8];
            }
            #pragma unroll
            for (int mb = 0; mb < 2; mb++)
                #pragma unroll
                for (int nb = 0; nb < 8; nb++)
                    MMA_F16(acc[mb][nb], ah[mb], bf[nb]);
            #pragma unroll
            for (int mb = 0; mb < 2; mb++)
                #pragma unroll
                for (int nb = 0; nb < 8; nb++)
                    MMA_F16(acc[mb][nb], al[mb], bf[nb]);
        }
        __syncthreads();
    }

    // ---- epilogue ----
    #pragma unroll
    for (int mb = 0; mb < 2; mb++) {
        #pragma unroll
        for (int nb = 0; nb < 8; nb++) {
            const int col = wn * 64 + nb * 8 + qc * 2;
            const int n = n0 + col;
            const float bv0 = bias[n];
            const float bv1 = bias[n + 1];
            #pragma unroll
            for (int half = 0; half < 2; half++) {
                const int m = m0 + wm * 32 + mb * 16 + qr + half * 8;
                float v0 = acc[mb][nb][half*2+0] + bv0;
                float v1 = acc[mb][nb][half*2+1] + bv1;
                if (MODE == 0) {
                    const int b = m >> 11, t = m & (Ts - 1);
                    const int which = n >> 10;
                    const int cn = n & (Cc - 1);
                    const int h = cn >> 6, d = cn & 63;
                    const size_t bh_ = (size_t)(b * Hh + h);
                    __half h0, l0, h1, l1;
                    if (which == 0) {
                        split2h(v0 * 0.125f, h0, l0);
                        split2h(v1 * 0.125f, h1, l1);
                        const size_t idx = (bh_ * Ts + t) * Dd + d;
                        *(uint32_t*)&g_qhi[idx] = pack2h(h0, h1);
                        *(uint32_t*)&g_qlo[idx] = pack2h(l0, l1);
                    } else if (which == 1) {
                        split2h(v0, h0, l0);
                        split2h(v1, h1, l1);
                        const size_t idx = (bh_ * Ts + t) * Dd + d;
                        *(uint32_t*)&g_khi[idx] = pack2h(h0, h1);
                        *(uint32_t*)&g_klo[idx] = pack2h(l0, l1);
                    } else {
                        const size_t i0 = (bh_ * Dd + d) * Ts + t;
                        const size_t i1 = (bh_ * Dd + d + 1) * Ts + t;
                        g_vt[i0] = __float2half_rn(v0);
                        g_vt[i1] = __float2half_rn(v1);
                    }
                } else {
                    outp[(size_t)m * N + n]     = v0;
                    outp[(size_t)m * N + n + 1] = v1;
                }
            }
        }
    }
}

// ---------------------------------------------------------------------------
// MMA flash attention: QK 3-product fp16 (Q hi/lo x K hi/lo), PV 2-product
// (P hi/lo x V single). cp.async double-buffered K/V tiles.
// ---------------------------------------------------------------------------
#define SPAD 72
#define AT_ARR_E (64 * SPAD)
#define AT_ARR_B (AT_ARR_E * 2)
#define AT_STAGE_B (3 * AT_ARR_B)        // Khi, Klo, V
#define ATTN_SMEM (2 * AT_STAGE_B)       // 55296 bytes

__global__ __launch_bounds__(128)
void attn_kernel()
{
    extern __shared__ __align__(16) char asmem_raw[];
    __half* smem = (__half*)asmem_raw;
    const uint32_t sbase = smem_to_u32(asmem_raw);

    const int tid = threadIdx.x;
    const int l = tid & 31;
    const int wm = tid >> 5;
    const int qr = l >> 2;
    const int qc = l & 3;
    const int qt = blockIdx.x;
    const int bh = blockIdx.y;

    const size_t qk_base = (size_t)bh * Ts * Dd;
    const size_t vt_base = (size_t)bh * Dd * Ts;

    auto issueKV = [&](int stage, int kt) {
        const uint32_t s0 = sbase + (uint32_t)stage * AT_STAGE_B;
        #pragma unroll
        for (int rep = 0; rep < 4; rep++) {
            const int i = tid + rep * 128;
            const int row = i >> 3;
            const int seg = (i & 7) * 8;
            const uint32_t so = (uint32_t)(row * SPAD + seg) * 2;
            const size_t gk = qk_base + (size_t)(kt * 64 + row) * Dd + seg;
            const size_t gv = vt_base + (size_t)row * Ts + kt * 64 + seg;
            CP16(s0 + 0u*AT_ARR_B + so, g_khi + gk);
            CP16(s0 + 1u*AT_ARR_B + so, g_klo + gk);
            CP16(s0 + 2u*AT_ARR_B + so, g_vt + gv);
        }
        CP_COMMIT();
    };

    uint32_t qh[4][4], ql[4][4];
    {
        const int r0 = qt * 64 + wm * 16 + qr;
        #pragma unroll
        for (int ks = 0; ks < 4; ks++) {
            const int kcol = ks * 16 + qc * 2;
            qh[ks][0] = *(const uint32_t*)&g_qhi[qk_base + (size_t)r0 * Dd + kcol];
            qh[ks][1] = *(const uint32_t*)&g_qhi[qk_base + (size_t)(r0 + 8) * Dd + kcol];
            qh[ks][2] = *(const uint32_t*)&g_qhi[qk_base + (size_t)r0 * Dd + kcol + 8];
            qh[ks][3] = *(const uint32_t*)&g_qhi[qk_base + (size_t)(r0 + 8) * Dd + kcol + 8];
            ql[ks][0] = *(const uint32_t*)&g_qlo[qk_base + (size_t)r0 * Dd + kcol];
            ql[ks][1] = *(const uint32_t*)&g_qlo[qk_base + (size_t)(r0 + 8) * Dd + kcol];
            ql[ks][2] = *(const uint32_t*)&g_qlo[qk_base + (size_t)r0 * Dd + kcol + 8];
            ql[ks][3] = *(const uint32_t*)&g_qlo[qk_base + (size_t)(r0 + 8) * Dd + kcol + 8];
        }
    }

    float o[8][4];
    #pragma unroll
    for (int i = 0; i < 8; i++)
        #pragma unroll
        for (int j = 0; j < 4; j++) o[i][j] = 0.f;
    float m0v = -1e30f, m1v = -1e30f, l0v = 0.f, l1v = 0.f;

    issueKV(0, 0);

    for (int kt = 0; kt <= qt; kt++) {
        if (kt + 1 <= qt) { issueKV((kt + 1) & 1, kt + 1); CP_WAIT1(); }
        else              { CP_WAIT0(); }
        __syncthreads();

        const __half* sKh = smem + (size_t)(kt & 1) * (AT_STAGE_B / 2);
        const __half* sKl = sKh + AT_ARR_E;
        const __half* sV  = sKh + 2 * AT_ARR_E;

        // ---- S = Q K^T (3-product: qh*kh, qh*kl, ql*kh) ----
        float c[8][4];
        #pragma unroll
        for (int nb = 0; nb < 8; nb++)
            #pragma unroll
            for (int q = 0; q < 4; q++) c[nb][q] = 0.f;

        #pragma unroll
        for (int ks = 0; ks < 4; ks++) {
            const int kb = ks * 16 + qc * 2;
            uint32_t bhf[8][2], blf[8][2];
            #pragma unroll
            for (int nb = 0; nb < 8; nb++) {
                const int nrow = nb * 8 + qr;
                bhf[nb][0] = *(const uint32_t*)&sKh[nrow * SPAD + kb];
                bhf[nb][1] = *(const uint32_t*)&sKh[nrow * SPAD + kb + 8];
                blf[nb][0] = *(const uint32_t*)&sKl[nrow * SPAD + kb];
                blf[nb][1] = *(const uint32_t*)&sKl[nrow * SPAD + kb + 8];
            }
            #pragma unroll
            for (int nb = 0; nb < 8; nb++) MMA_F16(c[nb], qh[ks], bhf[nb]);
            #pragma unroll
            for (int nb = 0; nb < 8; nb++) MMA_F16(c[nb], qh[ks], blf[nb]);
            #pragma unroll
            for (int nb = 0; nb < 8; nb++) MMA_F16(c[nb], ql[ks], bhf[nb]);
        }

        if (kt == qt) {
            const int r0 = qt * 64 + wm * 16 + qr;
            #pragma unroll
            for (int nb = 0; nb < 8; nb++) {
                const int col = kt * 64 + nb * 8 + qc * 2;
                if (col > r0)     c[nb][0] = -1e30f;
                if (col + 1 > r0) c[nb][1] = -1e30f;
                if (col > r0 + 8)     c[nb][2] = -1e30f;
                if (col + 1 > r0 + 8) c[nb][3] = -1e30f;
            }
        }

        float rmax0 = -1e30f, rmax1 = -1e30f;
        #pragma unroll
        for (int nb = 0; nb < 8; nb++) {
            rmax0 = fmaxf(rmax0, fmaxf(c[nb][0], c[nb][1]));
            rmax1 = fmaxf(rmax1, fmaxf(c[nb][2], c[nb][3]));
        }
        #pragma unroll
        for (int off = 1; off <= 2; off <<= 1) {
            rmax0 = fmaxf(rmax0, __shfl_xor_sync(0xffffffffu, rmax0, off));
            rmax1 = fmaxf(rmax1, __shfl_xor_sync(0xffffffffu, rmax1, off));
        }
        const float mn0 = fmaxf(m0v, rmax0);
        const float mn1 = fmaxf(m1v, rmax1);
        const float cf0 = __expf(m0v - mn0);
        const float cf1 = __expf(m1v - mn1);
        m0v = mn0; m1v = mn1;

        float s0 = 0.f, s1 = 0.f;
        #pragma unroll
        for (int nb = 0; nb < 8; nb++) {
            c[nb][0] = __expf(c[nb][0] - mn0); s0 += c[nb][0];
            c[nb][1] = __expf(c[nb][1] - mn0); s0 += c[nb][1];
            c[nb][2] = __expf(c[nb][2] - mn1); s1 += c[nb][2];
            c[nb][3] = __expf(c[nb][3] - mn1); s1 += c[nb][3];
        }
        #pragma unroll
        for (int off = 1; off <= 2; off <<= 1) {
            s0 += __shfl_xor_sync(0xffffffffu, s0, off);
            s1 += __shfl_xor_sync(0xffffffffu, s1, off);
        }
        l0v = l0v * cf0 + s0;
        l1v = l1v * cf1 + s1;
        #pragma unroll
        for (int i = 0; i < 8; i++) {
            o[i][0] *= cf0; o[i][1] *= cf0;
            o[i][2] *= cf1; o[i][3] *= cf1;
        }

        // ---- P fragments in-register, fp16 hi/lo split ----
        uint32_t ph[4][4], pl[4][4];
        #pragma unroll
        for (int ks2 = 0; ks2 < 4; ks2++) {
            #pragma unroll
            for (int part = 0; part < 4; part++) {
                const int nb = 2 * ks2 + (part >> 1);
                const int base = (part & 1) * 2;
                const int aidx = (part >> 1) * 2 + (part & 1);
                const float v0 = c[nb][base + 0];
                const float v1 = c[nb][base + 1];
                __half h0, lo0, h1, lo1;
                split2h(v0, h0, lo0);
                split2h(v1, h1, lo1);
                ph[ks2][aidx] = pack2h(h0, h1);
                pl[ks2][aidx] = pack2h(lo0, lo1);
            }
        }

        // ---- O += P @ V (2-product: ph*v, pl*v) ----
        #pragma unroll
        for (int ks2 = 0; ks2 < 4; ks2++) {
            const int kb = ks2 * 16 + qc * 2;
            uint32_t vf[8][2];
            #pragma unroll
            for (int nb2 = 0; nb2 < 8; nb2++) {
                const int nrow = nb2 * 8 + qr;
                vf[nb2][0] = *(const uint32_t*)&sV[nrow * SPAD + kb];
                vf[nb2][1] = *(const uint32_t*)&sV[nrow * SPAD + kb + 8];
            }
            #pragma unroll
            for (int nb2 = 0; nb2 < 8; nb2++) MMA_F16(o[nb2], ph[ks2], vf[nb2]);
            #pragma unroll
            for (int nb2 = 0; nb2 < 8; nb2++) MMA_F16(o[nb2], pl[ks2], vf[nb2]);
        }
        __syncthreads();
    }

    // ---- epilogue: normalize, fp16 split, write g_yhi/g_ylo ----
    const int b = bh >> 4, h = bh & 15;
    const float inv0 = 1.0f / l0v;
    const float inv1 = 1.0f / l1v;
    const int t0 = qt * 64 + wm * 16 + qr;
    #pragma unroll
    for (int nb2 = 0; nb2 < 8; nb2++) {
        const int d = nb2 * 8 + qc * 2;
        {
            const size_t idx = (size_t)(b * Ts + t0) * Cc + h * Dd + d;
            __half h0, lo0, h1, lo1;
            split2h(o[nb2][0] * inv0, h0, lo0);
            split2h(o[nb2][1] * inv0, h1, lo1);
            *(uint32_t*)&g_yhi[idx] = pack2h(h0, h1);
            *(uint32_t*)&g_ylo[idx] = pack2h(lo0, lo1);
        }
        {
            const size_t idx = (size_t)(b * Ts + t0 + 8) * Cc + h * Dd + d;
            __half h0, lo0, h1, lo1;
            split2h(o[nb2][2] * inv1, h0, lo0);
            split2h(o[nb2][3] * inv1, h1, lo1);
            *(uint32_t*)&g_yhi[idx] = pack2h(h0, h1);
            *(uint32_t*)&g_ylo[idx] = pack2h(lo0, lo1);
        }
    }
}

// ---------------------------------------------------------------------------
extern "C" void kernel_launch(void* const* d_in, const int* in_sizes, int n_in,
                              void* d_out, int out_size)
{
    (void)in_sizes; (void)n_in; (void)out_size;
    const float* x     = (const float*)d_in[0];
    const float* w_qkv = (const float*)d_in[1];
    const float* b_qkv = (const float*)d_in[2];
    const float* w_out = (const float*)d_in[3];
    const float* b_out = (const float*)d_in[4];
    float* out = (float*)d_out;

    cudaFuncSetAttribute(gemm_mma<0, Nqkv>,
                         cudaFuncAttributeMaxDynamicSharedMemorySize, GEMM_SMEM);
    cudaFuncSetAttribute(gemm_mma<1, Cc>,
                         cudaFuncAttributeMaxDynamicSharedMemorySize, GEMM_SMEM);
    cudaFuncSetAttribute(attn_kernel,
                         cudaFuncAttributeMaxDynamicSharedMemorySize, ATTN_SMEM);

    // 0) Pre-split x (fp16 hi/lo) and weights (single fp16, transposed)
    split_x_kernel<<<(Mtot*Kdim)/(256*4), 256>>>(x);
    transpose_half_kernel<0, Nqkv><<<dim3(Nqkv/32, Kdim/32), dim3(32,8)>>>(w_qkv);
    transpose_half_kernel<1, Cc><<<dim3(Cc/32, Kdim/32), dim3(32,8)>>>(w_out);

    // 1) QKV projection (2-product fp16 MMA)
    gemm_mma<0, Nqkv><<<dim3(Nqkv/BN, Mtot/BM), 256, GEMM_SMEM>>>(b_qkv, nullptr);

    // 2) MMA flash attention (QK 3-product, PV 2-product)
    attn_kernel<<<dim3(Ts/64, Bb*Hh), 128, ATTN_SMEM>>>();

    // 3) Output projection (2-product fp16 MMA)
    gemm_mma<1, Cc><<<dim3(Cc/BN, Mtot/BM), 256, GEMM_SMEM>>>(b_out, out);
}